// round 10
// baseline (speedup 1.0000x reference)
#include <cuda_runtime.h>
#include <cuda_bf16.h>

// Problem constants (fixed by the reference).
#define B_   16
#define S_   1024
#define H_   256
#define TOUT 4096          // S * D_MAX
#define NBIN 256
#define ROWS (B_ * TOUT)

// Scratch (device globals: no allocation allowed).
__device__ int g_src[ROWS];        // frame -> phoneme index (valid for j < len)
__device__ int g_len[B_];          // per-batch expanded length

// ---------------------------------------------------------------------------
// Kernel 1: per-batch inclusive cumsum of rounded durations, scatter the
// frame->phoneme map (inverse of searchsorted-right), emit lengths.
// ---------------------------------------------------------------------------
__global__ void scan_scatter_kernel(const float* __restrict__ dur,
                                    float* __restrict__ out,
                                    long long out_size) {
    const int b = blockIdx.x;
    const int i = threadIdx.x;

    int d = (int)rintf(dur[b * S_ + i]);
    d = max(d, 0);

    const int lane = i & 31, warp = i >> 5;
    int v = d;
#pragma unroll
    for (int o = 1; o < 32; o <<= 1) {
        int n = __shfl_up_sync(0xffffffffu, v, o);
        if (lane >= o) v += n;
    }
    __shared__ int wsum[32];
    if (lane == 31) wsum[warp] = v;
    __syncthreads();
    if (warp == 0) {
        int w = wsum[lane];
#pragma unroll
        for (int o = 1; o < 32; o <<= 1) {
            int n = __shfl_up_sync(0xffffffffu, w, o);
            if (lane >= o) w += n;
        }
        wsum[lane] = w;
    }
    __syncthreads();
    const int csum  = v + (warp > 0 ? wsum[warp - 1] : 0);  // inclusive
    const int start = csum - d;

    for (int j = start; j < csum; ++j)
        g_src[b * TOUT + j] = i;

    if (i == S_ - 1) {
        g_len[b] = csum;
        if (out_size >= (long long)ROWS * H_ + B_)
            out[out_size - B_ + b] = (float)csum;   // lengths at tuple tail
    }
}

// ---------------------------------------------------------------------------
// Quantize: jnp.searchsorted(linspace(vmin,vmax,256), clip(v), 'left'),
// clipped to [0,255]. Closed-form ceil with +-1 fixup vs exact boundaries.
// ---------------------------------------------------------------------------
__device__ __forceinline__ int qbin(float v, float vmin, float vmax,
                                    float invstep, float step) {
    v = fminf(fmaxf(v, vmin), vmax);
    int k = (int)ceilf((v - vmin) * invstep);
    k = min(max(k, 0), NBIN - 1);
    if (k > 0 && (vmin + (float)(k - 1) * step) >= v) k--;
    else if ((vmin + (float)k * step) < v) k = min(k + 1, NBIN - 1);
    return k;
}

// ---------------------------------------------------------------------------
// Kernel 2: persistent grid-stride. One warp processes ~7-8 rows; the next
// row's uniform scalars (src / pitch / energy) are prefetched before the
// current row's vector work so the dependent scalar-load level of iteration
// i+1 overlaps with the vector loads/stores of iteration i. Single dispatch
// wave (1184 blocks ~= 8 CTAs/SM) removes CTA churn.
// ---------------------------------------------------------------------------
__global__ void __launch_bounds__(256, 6)
expand_gs_kernel(const float4* __restrict__ enc,
                 const float*  __restrict__ pitch_t,
                 const float*  __restrict__ energy_t,
                 const float4* __restrict__ ptab,
                 const float4* __restrict__ etab,
                 float4*       __restrict__ out) {
    const int lane   = threadIdx.x & 31;
    const int wid0   = (blockIdx.x * blockDim.x + threadIdx.x) >> 5;
    const int nwarps = (gridDim.x * blockDim.x) >> 5;

    int w = wid0;
    if (w >= ROWS) return;

    // Prologue: scalars for the first row.
    int   s_cur = g_src[w];
    float p_cur = __ldg(pitch_t + w);
    float e_cur = __ldg(energy_t + w);

    for (; w < ROWS; ) {
        const int wn = w + nwarps;
        // Prefetch next iteration's scalars (independent loads, issued early).
        int   s_nxt = 0; float p_nxt = 0.f, e_nxt = 0.f;
        if (wn < ROWS) {
            s_nxt = g_src[wn];
            p_nxt = __ldg(pitch_t + wn);
            e_nxt = __ldg(energy_t + wn);
        }

        const int b = w >> 12;            // / TOUT
        const int j = w & (TOUT - 1);
        const size_t rowo = (size_t)w * (H_ / 4);

        if (j >= g_len[b]) {
            const float4 z = make_float4(0.f, 0.f, 0.f, 0.f);
            out[rowo + lane]      = z;
            out[rowo + lane + 32] = z;
        } else {
            const int pb = qbin(p_cur, 50.0f, 400.0f, 255.0f / 350.0f, 350.0f / 255.0f);
            const int eb = qbin(e_cur,  0.0f,   1.0f, 255.0f,          1.0f / 255.0f);

            const float4* __restrict__ er = enc  + ((size_t)(b * S_ + s_cur)) * (H_ / 4);
            const float4* __restrict__ pr = ptab + (size_t)pb * (H_ / 4);
            const float4* __restrict__ qr = etab + (size_t)eb * (H_ / 4);

            const float4 a0 = er[lane];
            const float4 p0 = pr[lane];
            const float4 q0 = qr[lane];
            const float4 a1 = er[lane + 32];
            const float4 p1 = pr[lane + 32];
            const float4 q1 = qr[lane + 32];

            out[rowo + lane] = make_float4(a0.x + p0.x + q0.x,
                                           a0.y + p0.y + q0.y,
                                           a0.z + p0.z + q0.z,
                                           a0.w + p0.w + q0.w);
            out[rowo + lane + 32] = make_float4(a1.x + p1.x + q1.x,
                                                a1.y + p1.y + q1.y,
                                                a1.z + p1.z + q1.z,
                                                a1.w + p1.w + q1.w);
        }

        w = wn;
        s_cur = s_nxt; p_cur = p_nxt; e_cur = e_nxt;
    }
}

extern "C" void kernel_launch(void* const* d_in, const int* in_sizes, int n_in,
                              void* d_out, int out_size) {
    const float* enc      = (const float*)d_in[0];   // [B,S,H]
    const float* pitch_t  = (const float*)d_in[1];   // [B,TOUT]
    const float* energy_t = (const float*)d_in[2];   // [B,TOUT]
    const float* dur      = (const float*)d_in[3];   // [B,S]
    const float* ptab     = (const float*)d_in[4];   // [256,H]
    const float* etab     = (const float*)d_in[5];   // [256,H]
    float* out            = (float*)d_out;

    scan_scatter_kernel<<<B_, S_>>>(dur, out, (long long)out_size);

    // Single-wave persistent grid: ~8 CTAs per SM on 148 SMs.
    const int blocks = 1184;
    expand_gs_kernel<<<blocks, 256>>>((const float4*)enc, pitch_t, energy_t,
                                      (const float4*)ptab, (const float4*)etab,
                                      (float4*)out);
}